// round 1
// baseline (speedup 1.0000x reference)
#include <cuda_runtime.h>
#include <math.h>

#define NB 8
#define P  2048
#define EPSV 0.1f
#define KSCALE 14.426950408889634f   /* log2(e)/eps */

// ---------------- device scratch (no allocations allowed) ----------------
__device__ float g_xm[NB*P*2];
__device__ float g_ym[NB*P*2];
__device__ float g_sx[NB*P];
__device__ float g_sy[NB*P];
__device__ float g_logmu[NB*P];
__device__ float g_lognu[NB*P];
__device__ float g_u[NB*P];
__device__ float g_v[NB*P];
__device__ float g_part[NB*P];

__device__ __forceinline__ float ex2f(float x){
    float y; asm("ex2.approx.ftz.f32 %0, %1;" : "=f"(y) : "f"(x)); return y;
}

// ---------------- init: mask, marginals, norms, potentials=0 -------------
__global__ void __launch_bounds__(512) init_k(const float* __restrict__ x,
                                              const float* __restrict__ y)
{
    int n = blockIdx.x, tid = threadIdx.x;
    __shared__ float sS[512], sT[512];
    float locS = 0.f, locT = 0.f;
    for (int i = tid; i < P; i += 512) {
        int idx = (n*P + i)*2;
        float x0 = x[idx], x1 = x[idx+1];
        float y0 = y[idx], y1 = y[idx+1];
        // mask from x, applied to BOTH x and y (reference semantics)
        float m0 = (x0 != -1.0f) ? 1.0f : 0.0f;
        float m1 = (x1 != -1.0f) ? 1.0f : 0.0f;
        float xm0 = x0*m0, xm1 = x1*m1;
        float ym0 = y0*m0, ym1 = y1*m1;
        g_xm[idx] = xm0; g_xm[idx+1] = xm1;
        g_ym[idx] = ym0; g_ym[idx+1] = ym1;
        g_sx[n*P+i] = xm0*xm0 + xm1*xm1;
        g_sy[n*P+i] = ym0*ym0 + ym1*ym1;
        locS += xm1*xm1;
        locT += ym1*ym1;
    }
    sS[tid] = locS; sT[tid] = locT;
    __syncthreads();
    for (int s = 256; s > 0; s >>= 1) {
        if (tid < s) { sS[tid] += sS[tid+s]; sT[tid] += sT[tid+s]; }
        __syncthreads();
    }
    float S = sS[0], T = sT[0];
    for (int i = tid; i < P; i += 512) {
        int idx = (n*P + i)*2;
        float xm1 = g_xm[idx+1], ym1 = g_ym[idx+1];
        g_logmu[n*P+i] = logf(xm1*xm1/S + 1e-8f);
        g_lognu[n*P+i] = logf(ym1*ym1/T + 1e-8f);
        g_u[n*P+i] = 0.f;
        g_v[n*P+i] = 0.f;
    }
}

// ---------------- one Sinkhorn half-step (u- or v-update) ----------------
// dir==0: update u, reduce over y side.  dir==1: update v, reduce over x side.
// grid: (64, NB), block 256.  Each warp owns 4 rows; peer side staged in smem.
__global__ void __launch_bounds__(256) phase_k(int dir)
{
    __shared__ float shy0[P], shy1[P], shb[P];
    const float* pts_self = dir ? g_ym    : g_xm;
    const float* s_self   = dir ? g_sy    : g_sx;
    const float* logm     = dir ? g_lognu : g_logmu;
    float*       pot_self = dir ? g_v     : g_u;
    const float* pts_peer = dir ? g_xm    : g_ym;
    const float* s_peer   = dir ? g_sx    : g_sy;
    const float* pot_peer = dir ? g_u     : g_v;

    int n = blockIdx.y, bp = n*P;
    int tid = threadIdx.x, w = tid >> 5, lane = tid & 31;

    for (int j = tid; j < P; j += 256) {
        float2 yy = ((const float2*)pts_peer)[bp + j];
        shy0[j] = yy.x; shy1[j] = yy.y;
        shb[j]  = (pot_peer[bp+j] - s_peer[bp+j]) * KSCALE;
    }
    __syncthreads();

    int r0 = blockIdx.x*32 + w*4;
    float a[4], c0[4], c1[4], sum[4], uo[4];
#pragma unroll
    for (int k = 0; k < 4; k++) {
        int i = r0 + k;
        float2 xx = ((const float2*)pts_self)[bp + i];
        uo[k] = pot_self[bp+i];
        a[k]  = (uo[k] - s_self[bp+i]) * KSCALE;
        c0[k] = 2.0f*KSCALE*xx.x;
        c1[k] = 2.0f*KSCALE*xx.y;
        sum[k] = 0.f;
    }

    for (int j = lane; j < P; j += 32) {
        float y0 = shy0[j], y1 = shy1[j], b = shb[j];
#pragma unroll
        for (int k = 0; k < 4; k++) {
            float t = fmaf(c0[k], y0, fmaf(c1[k], y1, a[k] + b));
            sum[k] += ex2f(t);   // sum of exp(M): args bounded, no max-shift needed
        }
    }

#pragma unroll
    for (int k = 0; k < 4; k++) {
        float s = sum[k];
#pragma unroll
        for (int off = 16; off; off >>= 1) s += __shfl_xor_sync(0xffffffffu, s, off);
        if (lane == 0) {
            float lse = logf(fmaxf(s, 1e-35f));
            int i = r0 + k;
            pot_self[bp+i] = EPSV*(logm[bp+i] - lse) + uo[k];
        }
    }
}

// ---------------- finalize: write pi, C, per-row cost partials ----------
__global__ void __launch_bounds__(256) final_k(float* __restrict__ out)
{
    int n = blockIdx.y, i = blockIdx.x, tid = threadIdx.x;
    int bp = n*P;
    float2 xx = ((const float2*)g_xm)[bp + i];
    float u = g_u[bp + i];
    size_t base = ((size_t)bp + i) * P;
    float* out_pi = out + 8;
    float* out_C  = out + 8 + (size_t)NB*P*P;
    float acc = 0.f;
    for (int j = tid; j < P; j += 256) {
        float2 yy = ((const float2*)g_ym)[bp + j];
        float dx = xx.x - yy.x, dy = xx.y - yy.y;
        float C  = dx*dx + dy*dy;
        float pi = ex2f((u + g_v[bp+j] - C) * KSCALE);
        out_pi[base + j] = pi;
        out_C[base + j]  = C;
        acc = fmaf(pi, C, acc);
    }
    __shared__ float sred[256];
    sred[tid] = acc;
    __syncthreads();
    for (int s = 128; s > 0; s >>= 1) {
        if (tid < s) sred[tid] += sred[tid + s];
        __syncthreads();
    }
    if (tid == 0) g_part[bp + i] = sred[0];
}

// deterministic per-batch cost reduction (no float atomics)
__global__ void __launch_bounds__(256) cost_k(float* __restrict__ out)
{
    int n = blockIdx.x, tid = threadIdx.x;
    float acc = 0.f;
    for (int i = tid; i < P; i += 256) acc += g_part[n*P + i];
    __shared__ float sred[256];
    sred[tid] = acc;
    __syncthreads();
    for (int s = 128; s > 0; s >>= 1) {
        if (tid < s) sred[tid] += sred[tid + s];
        __syncthreads();
    }
    if (tid == 0) out[n] = sred[0];
}

// ---------------- launch ------------------------------------------------
extern "C" void kernel_launch(void* const* d_in, const int* in_sizes, int n_in,
                              void* d_out, int out_size)
{
    const float* x = (const float*)d_in[0];
    const float* y = (const float*)d_in[1];
    float* out = (float*)d_out;

    init_k<<<NB, 512>>>(x, y);
    for (int it = 0; it < 50; it++) {
        phase_k<<<dim3(64, NB), 256>>>(0);  // u-update
        phase_k<<<dim3(64, NB), 256>>>(1);  // v-update
    }
    final_k<<<dim3(P, NB), 256>>>(out);
    cost_k<<<NB, 256>>>(out);
}

// round 2
// speedup vs baseline: 1.9367x; 1.9367x over previous
#include <cuda_runtime.h>
#include <math.h>

#define NB 8
#define P  2048
#define EPSV 0.1f
#define KSCALE 14.426950408889634f   /* log2(e)/eps */
#define K2     28.853900817779268f   /* 2*KSCALE */

// ---------------- device scratch (no allocations allowed) ----------------
__device__ float g_xm[NB*P*2];
__device__ float g_ym[NB*P*2];
__device__ float g_sx[NB*P];
__device__ float g_sy[NB*P];
__device__ float g_logmu[NB*P];
__device__ float g_lognu[NB*P];
__device__ float g_u[NB*P];
__device__ float g_v[NB*P];
__device__ float g_part[NB*P];

__device__ __forceinline__ float ex2f(float x){
    float y; asm("ex2.approx.ftz.f32 %0, %1;" : "=f"(y) : "f"(x)); return y;
}

// ---------------- init: mask, marginals, norms, potentials=0 -------------
__global__ void __launch_bounds__(512) init_k(const float* __restrict__ x,
                                              const float* __restrict__ y)
{
    int n = blockIdx.x, tid = threadIdx.x;
    __shared__ float sS[512], sT[512];
    float locS = 0.f, locT = 0.f;
    for (int i = tid; i < P; i += 512) {
        int idx = (n*P + i)*2;
        float x0 = x[idx], x1 = x[idx+1];
        float y0 = y[idx], y1 = y[idx+1];
        float m0 = (x0 != -1.0f) ? 1.0f : 0.0f;
        float m1 = (x1 != -1.0f) ? 1.0f : 0.0f;
        float xm0 = x0*m0, xm1 = x1*m1;
        float ym0 = y0*m0, ym1 = y1*m1;
        g_xm[idx] = xm0; g_xm[idx+1] = xm1;
        g_ym[idx] = ym0; g_ym[idx+1] = ym1;
        g_sx[n*P+i] = xm0*xm0 + xm1*xm1;
        g_sy[n*P+i] = ym0*ym0 + ym1*ym1;
        locS += xm1*xm1;
        locT += ym1*ym1;
    }
    sS[tid] = locS; sT[tid] = locT;
    __syncthreads();
    for (int s = 256; s > 0; s >>= 1) {
        if (tid < s) { sS[tid] += sS[tid+s]; sT[tid] += sT[tid+s]; }
        __syncthreads();
    }
    float S = sS[0], T = sT[0];
    for (int i = tid; i < P; i += 512) {
        int idx = (n*P + i)*2;
        float xm1 = g_xm[idx+1], ym1 = g_ym[idx+1];
        g_logmu[n*P+i] = logf(xm1*xm1/S + 1e-8f);
        g_lognu[n*P+i] = logf(ym1*ym1/T + 1e-8f);
        g_u[n*P+i] = 0.f;
        g_v[n*P+i] = 0.f;
    }
}

// ---------------- one Sinkhorn half-step (u- or v-update) ----------------
// dir==0: update u (reduce over y side). dir==1: update v (reduce over x side).
// Identity used: u_new_i = sx_i + EPS*(logmu_i - ln Σ_j exp2(b_j + dot_ij)),
// with b_j = (pot_peer_j - s_peer_j)*KSCALE, dot_ij = 2*KSCALE*(x_i·y_j).
// Block 256 = 8 warps; warp (g, jh): 4 rows (group g), half the j range (jh).
// grid: (P/16, NB).
__global__ void __launch_bounds__(256) phase_k(int dir)
{
    __shared__ float2 shy[P];
    __shared__ float  shb[P];
    __shared__ float  sred[2][16];

    const float* pts_self = dir ? g_ym    : g_xm;
    const float* s_self   = dir ? g_sy    : g_sx;
    const float* logm     = dir ? g_lognu : g_logmu;
    float*       pot_self = dir ? g_v     : g_u;
    const float* pts_peer = dir ? g_xm    : g_ym;
    const float* s_peer   = dir ? g_sx    : g_sy;
    const float* pot_peer = dir ? g_u     : g_v;

    int n = blockIdx.y, bp = n*P;
    int tid = threadIdx.x, w = tid >> 5, lane = tid & 31;

    for (int j = tid; j < P; j += 256) {
        shy[j] = ((const float2*)pts_peer)[bp + j];
        shb[j] = (pot_peer[bp+j] - s_peer[bp+j]) * KSCALE;
    }
    __syncthreads();

    int g  = w & 3;       // row group within block
    int jh = w >> 2;      // which half of j
    int r0 = blockIdx.x*16 + g*4;

    float c0[4], c1[4], sum[4];
#pragma unroll
    for (int k = 0; k < 4; k++) {
        float2 xx = ((const float2*)pts_self)[bp + r0 + k];
        c0[k] = K2 * xx.x;
        c1[k] = K2 * xx.y;
        sum[k] = 0.f;
    }

    int jend = jh*1024 + 1024;
#pragma unroll 4
    for (int j = jh*1024 + lane; j < jend; j += 32) {
        float2 yy = shy[j];
        float  b  = shb[j];
#pragma unroll
        for (int k = 0; k < 4; k++) {
            float t = fmaf(c0[k], yy.x, fmaf(c1[k], yy.y, b));
            sum[k] += ex2f(t);
        }
    }

#pragma unroll
    for (int k = 0; k < 4; k++) {
        float s = sum[k];
#pragma unroll
        for (int off = 16; off; off >>= 1) s += __shfl_xor_sync(0xffffffffu, s, off);
        if (lane == 0) sred[jh][g*4 + k] = s;
    }
    __syncthreads();

    if (tid < 16) {
        float s = sred[0][tid] + sred[1][tid];
        int i = blockIdx.x*16 + tid;
        pot_self[bp+i] = s_self[bp+i] + EPSV*(logm[bp+i] - logf(fmaxf(s, 1e-35f)));
    }
}

// ---------------- finalize: write pi, C, per-row cost partials ----------
__global__ void __launch_bounds__(256) final_k(float* __restrict__ out)
{
    int n = blockIdx.y, i = blockIdx.x, tid = threadIdx.x;
    int bp = n*P;
    float2 xx = ((const float2*)g_xm)[bp + i];
    float u = g_u[bp + i];
    size_t base = ((size_t)bp + i) * P;
    float* out_pi = out + 8;
    float* out_C  = out + 8 + (size_t)NB*P*P;
    float acc = 0.f;
    for (int j = tid; j < P; j += 256) {
        float2 yy = ((const float2*)g_ym)[bp + j];
        float dx = xx.x - yy.x, dy = xx.y - yy.y;
        float C  = dx*dx + dy*dy;
        float pi = ex2f((u + g_v[bp+j] - C) * KSCALE);
        out_pi[base + j] = pi;
        out_C[base + j]  = C;
        acc = fmaf(pi, C, acc);
    }
    __shared__ float sred[256];
    sred[tid] = acc;
    __syncthreads();
    for (int s = 128; s > 0; s >>= 1) {
        if (tid < s) sred[tid] += sred[tid + s];
        __syncthreads();
    }
    if (tid == 0) g_part[bp + i] = sred[0];
}

// deterministic per-batch cost reduction (no float atomics)
__global__ void __launch_bounds__(256) cost_k(float* __restrict__ out)
{
    int n = blockIdx.x, tid = threadIdx.x;
    float acc = 0.f;
    for (int i = tid; i < P; i += 256) acc += g_part[n*P + i];
    __shared__ float sred[256];
    sred[tid] = acc;
    __syncthreads();
    for (int s = 128; s > 0; s >>= 1) {
        if (tid < s) sred[tid] += sred[tid + s];
        __syncthreads();
    }
    if (tid == 0) out[n] = sred[0];
}

// ---------------- launch ------------------------------------------------
extern "C" void kernel_launch(void* const* d_in, const int* in_sizes, int n_in,
                              void* d_out, int out_size)
{
    const float* x = (const float*)d_in[0];
    const float* y = (const float*)d_in[1];
    float* out = (float*)d_out;

    init_k<<<NB, 512>>>(x, y);
    for (int it = 0; it < 50; it++) {
        phase_k<<<dim3(P/16, NB), 256>>>(0);  // u-update
        phase_k<<<dim3(P/16, NB), 256>>>(1);  // v-update
    }
    final_k<<<dim3(P, NB), 256>>>(out);
    cost_k<<<NB, 256>>>(out);
}